// round 2
// baseline (speedup 1.0000x reference)
#include <cuda_runtime.h>
#include <math.h>

// Problem shape (fixed)
#define BB 2
#define NN 2048
#define DD 1024
#define HH 16
#define HD 64
#define SCALE 0.125f   // HD^-0.5

// ---------------- scratch (no allocation allowed) ----------------
__device__ float g_q[(size_t)BB*HH*NN*HD];       // 16 MB, [b][h][n][hd]
__device__ float g_k[(size_t)BB*HH*NN*HD];
__device__ float g_v[(size_t)BB*HH*NN*HD];
__device__ float g_attnout[(size_t)BB*NN*DD];    // 16 MB, [b][n][d]
__device__ float g_bias[(size_t)BB*HH*NN];       // g * cov, [b][h][m]
__device__ float g_pooled[BB*DD];
__device__ float g_gate[BB];

// ---------------- tiny kernels ----------------
__global__ void zero_pooled_kernel() {
    int i = blockIdx.x * blockDim.x + threadIdx.x;
    if (i < BB*DD) g_pooled[i] = 0.f;
}

// x mean over N, split over n-chunks for parallelism; atomicAdd partials.
__global__ void pool_kernel(const float* __restrict__ x) {
    int b = blockIdx.y;
    int d = blockIdx.x * blockDim.x + threadIdx.x;
    int n0 = blockIdx.z * 128;
    const float* xp = x + ((size_t)b*NN + n0)*DD + d;
    float s = 0.f;
    #pragma unroll 4
    for (int n = 0; n < 128; n++) s += xp[(size_t)n*DD];
    atomicAdd(&g_pooled[b*DD + d], s * (1.0f/NN));
}

// g[b] = sigmoid( silu(pooled @ w_fg1 + b_fg1) @ w_fg2 + b_fg2 )
__global__ void gate_kernel(const float* __restrict__ w_fg1, const float* __restrict__ b_fg1,
                            const float* __restrict__ w_fg2, const float* __restrict__ b_fg2) {
    int b = blockIdx.x;
    int j = threadIdx.x;   // 256
    const float* p = g_pooled + b*DD;
    float acc = b_fg1[j];
    #pragma unroll 4
    for (int k = 0; k < DD; k++) acc += p[k] * w_fg1[k*256 + j];
    float hid = acc / (1.f + __expf(-acc));   // silu
    float part = hid * w_fg2[j];
    __shared__ float red[256];
    red[j] = part;
    __syncthreads();
    for (int s = 128; s > 0; s >>= 1) {
        if (j < s) red[j] += red[j + s];
        __syncthreads();
    }
    if (j == 0) g_gate[b] = 1.f / (1.f + __expf(-(red[0] + b_fg2[0])));
}

// bias[b][h][m] = g[b] * ( silu(cov*w_ce1 + b_ce1) @ w_ce2 + b_ce2 )[h]
__global__ void cov_kernel(const float* __restrict__ coverage,
                           const float* __restrict__ w_ce1, const float* __restrict__ b_ce1,
                           const float* __restrict__ w_ce2, const float* __restrict__ b_ce2) {
    int b = blockIdx.y;
    int m = blockIdx.x * blockDim.x + threadIdx.x;
    float c = coverage[b*NN + m];
    float g = g_gate[b];
    float acc[HH];
    #pragma unroll
    for (int h = 0; h < HH; h++) acc[h] = b_ce2[h];
    for (int j = 0; j < 256; j++) {
        float t = fmaf(c, w_ce1[j], b_ce1[j]);
        float hid = t / (1.f + __expf(-t));
        #pragma unroll
        for (int h = 0; h < HH; h++) acc[h] = fmaf(hid, w_ce2[j*HH + h], acc[h]);
    }
    #pragma unroll
    for (int h = 0; h < HH; h++) g_bias[((size_t)b*HH + h)*NN + m] = g * acc[h];
}

// ---------------- 128x128x8 register-blocked SGEMM ----------------
// MODE 0: A = x [4096,1024], B = w_qkv [1024,3072], scatter into g_q/g_k/g_v
// MODE 1: A = g_attnout [4096,1024], B = w_out [1024,1024], C = d_out (+ b_out)
template<int MODE>
__global__ __launch_bounds__(256) void sgemm_kernel(
    const float* __restrict__ A, const float* __restrict__ Bm,
    float* __restrict__ C, const float* __restrict__ bias, int Nn)
{
    const int K = DD;
    __shared__ __align__(16) float As[8][128];
    __shared__ __align__(16) float Bs[8][128];
    int tid = threadIdx.x;
    int m0 = blockIdx.y * 128;
    int n0 = blockIdx.x * 128;
    int ty = tid >> 4, tx = tid & 15;

    const float* Ap = (MODE == 1) ? g_attnout : A;

    float acc[8][8];
    #pragma unroll
    for (int i = 0; i < 8; i++)
        #pragma unroll
        for (int j = 0; j < 8; j++) acc[i][j] = 0.f;

    int arow = tid >> 1;
    int acol = (tid & 1) * 4;
    int brow = tid >> 5;
    int bcol = (tid & 31) * 4;
    const float* Aptr = Ap + (size_t)(m0 + arow)*K + acol;
    const float* Bptr = Bm + (size_t)brow*Nn + n0 + bcol;

    for (int k0 = 0; k0 < K; k0 += 8) {
        float4 av = *(const float4*)(Aptr + k0);
        float4 bv = *(const float4*)(Bptr + (size_t)k0*Nn);
        As[acol+0][arow] = av.x;
        As[acol+1][arow] = av.y;
        As[acol+2][arow] = av.z;
        As[acol+3][arow] = av.w;
        *(float4*)&Bs[brow][bcol] = bv;
        __syncthreads();
        #pragma unroll
        for (int kk = 0; kk < 8; kk++) {
            float a[8], bb[8];
            *(float4*)&a[0] = *(const float4*)&As[kk][ty*8];
            *(float4*)&a[4] = *(const float4*)&As[kk][ty*8+4];
            *(float4*)&bb[0] = *(const float4*)&Bs[kk][tx*8];
            *(float4*)&bb[4] = *(const float4*)&Bs[kk][tx*8+4];
            #pragma unroll
            for (int i = 0; i < 8; i++)
                #pragma unroll
                for (int j = 0; j < 8; j++)
                    acc[i][j] = fmaf(a[i], bb[j], acc[i][j]);
        }
        __syncthreads();
    }

    if (MODE == 0) {
        #pragma unroll
        for (int i = 0; i < 8; i++) {
            int r = m0 + ty*8 + i;
            int b = r >> 11;         // / 2048
            int n = r & 2047;
            #pragma unroll
            for (int j = 0; j < 8; j++) {
                int c = n0 + tx*8 + j;
                int part = c >> 10;
                int d = c & 1023;
                int h = d >> 6;
                int hd = d & 63;
                float* dst = (part == 0) ? g_q : (part == 1) ? g_k : g_v;
                dst[((((size_t)b*HH + h)*NN + n) << 6) + hd] = acc[i][j];
            }
        }
    } else {
        #pragma unroll
        for (int i = 0; i < 8; i++) {
            int r = m0 + ty*8 + i;
            float* Crow = C + (size_t)r*Nn;
            #pragma unroll
            for (int j = 0; j < 8; j++) {
                int c = n0 + tx*8 + j;
                Crow[c] = acc[i][j] + bias[c];
            }
        }
    }
}

// ---------------- flash attention: 64 queries/block, 64-key chunks ----------------
// Layouts in smem: sQ/sKP stored k-major [hd][token] with XOR swizzle; sV natural [c][d].
// sKP is reused for P (probabilities) after S compute.
__global__ __launch_bounds__(256) void flash_kernel() {
    __shared__ __align__(16) float sQ[64*64];
    __shared__ __align__(16) float sKP[64*64];
    __shared__ __align__(16) float sV[64*64];

    int tid = threadIdx.x;
    int b = blockIdx.z, h = blockIdx.y;
    int q0 = blockIdx.x * 64;
    const float* Qg = g_q + (((size_t)(b*HH + h))*NN + q0)*HD;
    const float* Kg = g_k + ((size_t)(b*HH + h))*NN*HD;
    const float* Vg = g_v + ((size_t)(b*HH + h))*NN*HD;
    const float* biasg = g_bias + (size_t)(b*HH + h)*NN;
    int ty = tid >> 4, tx = tid & 15;   // thread owns queries ty*4..+4, keys/dims tx*4..+4

    // Load Q, transposed (k-major) + swizzled
    #pragma unroll
    for (int r = 0; r < 16; r++) {
        int idx = tid + 256*r;
        int q = idx >> 6, kk = idx & 63;
        sQ[kk*64 + ((((q>>2) ^ (kk & 15)) << 2) | (q & 3))] = Qg[idx];
    }

    float m_run[4], l_run[4], acc[4][4];
    #pragma unroll
    for (int i = 0; i < 4; i++) {
        m_run[i] = -1e30f; l_run[i] = 0.f;
        #pragma unroll
        for (int j = 0; j < 4; j++) acc[i][j] = 0.f;
    }
    __syncthreads();

    for (int c0 = 0; c0 < NN; c0 += 64) {
        // Load K chunk (transposed+swizzled) and V chunk (natural)
        #pragma unroll
        for (int r = 0; r < 16; r++) {
            int idx = tid + 256*r;
            int c = idx >> 6, kk = idx & 63;
            sKP[kk*64 + ((((c>>2) ^ (kk & 15)) << 2) | (c & 3))] = Kg[(size_t)c0*64 + idx];
            sV[idx] = Vg[(size_t)c0*64 + idx];
        }
        float bv[4];
        #pragma unroll
        for (int j = 0; j < 4; j++) bv[j] = biasg[c0 + tx*4 + j];
        __syncthreads();

        // S = Q K^T for this 64x64 tile; thread computes 4x4
        float s[4][4];
        #pragma unroll
        for (int i = 0; i < 4; i++)
            #pragma unroll
            for (int j = 0; j < 4; j++) s[i][j] = 0.f;
        #pragma unroll 4
        for (int kk = 0; kk < 64; kk++) {
            float4 qv = *(const float4*)&sQ [kk*64 + ((ty ^ (kk & 15)) << 2)];
            float4 kv = *(const float4*)&sKP[kk*64 + ((tx ^ (kk & 15)) << 2)];
            float qa[4] = {qv.x, qv.y, qv.z, qv.w};
            float ka[4] = {kv.x, kv.y, kv.z, kv.w};
            #pragma unroll
            for (int i = 0; i < 4; i++)
                #pragma unroll
                for (int j = 0; j < 4; j++)
                    s[i][j] = fmaf(qa[i], ka[j], s[i][j]);
        }

        // Online softmax: scale + key-bias, row max/sum across 16-lane groups
        float ef[4];
        #pragma unroll
        for (int i = 0; i < 4; i++) {
            float rm = -1e30f;
            #pragma unroll
            for (int j = 0; j < 4; j++) {
                s[i][j] = fmaf(s[i][j], SCALE, bv[j]);
                rm = fmaxf(rm, s[i][j]);
            }
            #pragma unroll
            for (int msk = 8; msk >= 1; msk >>= 1)
                rm = fmaxf(rm, __shfl_xor_sync(0xffffffffu, rm, msk));
            float m_new = fmaxf(m_run[i], rm);
            ef[i] = __expf(m_run[i] - m_new);
            float rs = 0.f;
            #pragma unroll
            for (int j = 0; j < 4; j++) {
                s[i][j] = __expf(s[i][j] - m_new);
                rs += s[i][j];
            }
            #pragma unroll
            for (int msk = 8; msk >= 1; msk >>= 1)
                rs += __shfl_xor_sync(0xffffffffu, rs, msk);
            l_run[i] = l_run[i]*ef[i] + rs;
            m_run[i] = m_new;
            #pragma unroll
            for (int j = 0; j < 4; j++) acc[i][j] *= ef[i];
        }

        __syncthreads();   // everyone done reading K from sKP
        // store P into sKP (swizzled by query)
        #pragma unroll
        for (int i = 0; i < 4; i++) {
            int q = ty*4 + i;
            int sw = (q & 7) << 2;
            #pragma unroll
            for (int j = 0; j < 4; j++)
                sKP[q*64 + ((tx*4 + j) ^ sw)] = s[i][j];
        }
        __syncthreads();

        // acc += P @ V
        #pragma unroll 4
        for (int c = 0; c < 64; c++) {
            float4 vv = *(const float4*)&sV[c*64 + tx*4];
            float va[4] = {vv.x, vv.y, vv.z, vv.w};
            #pragma unroll
            for (int i = 0; i < 4; i++) {
                int q = ty*4 + i;
                float pv = sKP[q*64 + (c ^ ((q & 7) << 2))];
                #pragma unroll
                for (int j = 0; j < 4; j++)
                    acc[i][j] = fmaf(pv, va[j], acc[i][j]);
            }
        }
        __syncthreads();   // before next chunk overwrites sKP/sV
    }

    // normalize and write [b][n][h*64+hd]
    #pragma unroll
    for (int i = 0; i < 4; i++) {
        float inv = 1.0f / l_run[i];
        int q = q0 + ty*4 + i;
        float4 o;
        o.x = acc[i][0]*inv; o.y = acc[i][1]*inv;
        o.z = acc[i][2]*inv; o.w = acc[i][3]*inv;
        *(float4*)&g_attnout[((size_t)b*NN + q)*DD + h*HD + tx*4] = o;
    }
}

// ---------------- launch ----------------
extern "C" void kernel_launch(void* const* d_in, const int* in_sizes, int n_in,
                              void* d_out, int out_size) {
    const float* x        = (const float*)d_in[0];
    const float* coverage = (const float*)d_in[1];
    const float* w_qkv    = (const float*)d_in[2];
    const float* w_out    = (const float*)d_in[3];
    const float* b_out    = (const float*)d_in[4];
    const float* w_ce1    = (const float*)d_in[5];
    const float* b_ce1    = (const float*)d_in[6];
    const float* w_ce2    = (const float*)d_in[7];
    const float* b_ce2    = (const float*)d_in[8];
    const float* w_fg1    = (const float*)d_in[9];
    const float* b_fg1    = (const float*)d_in[10];
    const float* w_fg2    = (const float*)d_in[11];
    const float* b_fg2    = (const float*)d_in[12];
    float* out = (float*)d_out;

    // pooled gate path
    zero_pooled_kernel<<<(BB*DD + 255)/256, 256>>>();
    pool_kernel<<<dim3(DD/256, BB, NN/128), 256>>>(x);
    gate_kernel<<<BB, 256>>>(w_fg1, b_fg1, w_fg2, b_fg2);
    // coverage bias (needs gate)
    cov_kernel<<<dim3(NN/128, BB), 128>>>(coverage, w_ce1, b_ce1, w_ce2, b_ce2);
    // QKV projection
    sgemm_kernel<0><<<dim3(3*DD/128, BB*NN/128), 256>>>(x, w_qkv, nullptr, nullptr, 3*DD);
    // fused attention
    flash_kernel<<<dim3(NN/64, HH, BB), 256>>>();
    // output projection
    sgemm_kernel<1><<<dim3(DD/128, BB*NN/128), 256>>>(nullptr, w_out, out, b_out, DD);
}

// round 3
// speedup vs baseline: 2.0230x; 2.0230x over previous
#include <cuda_runtime.h>
#include <math.h>

// Problem shape (fixed)
#define BB 2
#define NN 2048
#define DD 1024
#define HH 16
#define HD 64
#define SCALE 0.125f   // HD^-0.5

// ---------------- scratch (no allocation allowed) ----------------
__device__ float g_q[(size_t)BB*HH*NN*HD];       // [b][h][n][hd]
__device__ float g_k[(size_t)BB*HH*NN*HD];
__device__ float g_v[(size_t)BB*HH*NN*HD];
__device__ float g_attnout[(size_t)BB*NN*DD];    // [b][n][d]
__device__ float g_bias[(size_t)BB*HH*NN];       // g * cov, [b][h][m]
__device__ float g_pooled[BB*DD];
__device__ float g_gate[BB];

// ---------------- tiny kernels ----------------
__global__ void zero_pooled_kernel() {
    int i = blockIdx.x * blockDim.x + threadIdx.x;
    if (i < BB*DD) g_pooled[i] = 0.f;
}

__global__ void pool_kernel(const float* __restrict__ x) {
    int b = blockIdx.y;
    int d = blockIdx.x * blockDim.x + threadIdx.x;
    int n0 = blockIdx.z * 128;
    const float* xp = x + ((size_t)b*NN + n0)*DD + d;
    float s = 0.f;
    #pragma unroll 4
    for (int n = 0; n < 128; n++) s += xp[(size_t)n*DD];
    atomicAdd(&g_pooled[b*DD + d], s * (1.0f/NN));
}

__global__ void gate_kernel(const float* __restrict__ w_fg1, const float* __restrict__ b_fg1,
                            const float* __restrict__ w_fg2, const float* __restrict__ b_fg2) {
    int b = blockIdx.x;
    int j = threadIdx.x;   // 256
    const float* p = g_pooled + b*DD;
    float acc = b_fg1[j];
    #pragma unroll 4
    for (int k = 0; k < DD; k++) acc += p[k] * w_fg1[k*256 + j];
    float hid = acc / (1.f + __expf(-acc));   // silu
    float part = hid * w_fg2[j];
    __shared__ float red[256];
    red[j] = part;
    __syncthreads();
    for (int s = 128; s > 0; s >>= 1) {
        if (j < s) red[j] += red[j + s];
        __syncthreads();
    }
    if (j == 0) g_gate[b] = 1.f / (1.f + __expf(-(red[0] + b_fg2[0])));
}

// warp-per-token coverage MLP: bias[b][h][m] = g[b]*(silu(c*w1+b1)@w2 + b2)[h]
__global__ __launch_bounds__(128) void cov_kernel2(
    const float* __restrict__ coverage,
    const float* __restrict__ w_ce1, const float* __restrict__ b_ce1,
    const float* __restrict__ w_ce2, const float* __restrict__ b_ce2) {
    int w = threadIdx.x >> 5, lane = threadIdx.x & 31;
    int m = blockIdx.x * 4 + w;
    int b = blockIdx.y;
    float c = coverage[b*NN + m];
    float g = g_gate[b];
    float acc[HH];
    #pragma unroll
    for (int h = 0; h < HH; h++) acc[h] = 0.f;
    #pragma unroll
    for (int t = 0; t < 8; t++) {
        int j = lane + 32*t;
        float tt = fmaf(c, w_ce1[j], b_ce1[j]);
        float hid = tt / (1.f + __expf(-tt));
        #pragma unroll
        for (int h = 0; h < HH; h++)
            acc[h] = fmaf(hid, w_ce2[j*HH + h], acc[h]);
    }
    #pragma unroll
    for (int mask = 16; mask >= 1; mask >>= 1)
        #pragma unroll
        for (int h = 0; h < HH; h++)
            acc[h] += __shfl_xor_sync(0xffffffffu, acc[h], mask);
    if (lane < HH)
        g_bias[((size_t)b*HH + lane)*NN + m] = g * (acc[lane] + b_ce2[lane]);
}

// ---------------- 128x128x8 double-buffered SGEMM ----------------
// MODE 0: A = x [4096,1024], B = w_qkv [1024,3072], scatter into g_q/g_k/g_v
// MODE 1: A = g_attnout [4096,1024], B = w_out [1024,1024], C = d_out (+ b_out)
template<int MODE>
__global__ __launch_bounds__(256) void sgemm_kernel(
    const float* __restrict__ A, const float* __restrict__ Bm,
    float* __restrict__ C, const float* __restrict__ bias, int Nn)
{
    const int K = DD;
    __shared__ __align__(16) float As[2][8][128];
    __shared__ __align__(16) float Bs[2][8][128];
    int tid = threadIdx.x;
    int m0 = blockIdx.y * 128;
    int n0 = blockIdx.x * 128;
    int ty = tid >> 4, tx = tid & 15;

    const float* Ap = (MODE == 1) ? g_attnout : A;

    float acc[8][8];
    #pragma unroll
    for (int i = 0; i < 8; i++)
        #pragma unroll
        for (int j = 0; j < 8; j++) acc[i][j] = 0.f;

    int arow = tid >> 1;
    int acol = (tid & 1) * 4;
    int brow = tid >> 5;
    int bcol = (tid & 31) * 4;
    const float* Aptr = Ap + (size_t)(m0 + arow)*K + acol;
    const float* Bptr = Bm + (size_t)brow*Nn + n0 + bcol;

    // prologue: load tile 0
    {
        float4 av = *(const float4*)(Aptr);
        float4 bv = *(const float4*)(Bptr);
        As[0][acol+0][arow] = av.x;
        As[0][acol+1][arow] = av.y;
        As[0][acol+2][arow] = av.z;
        As[0][acol+3][arow] = av.w;
        *(float4*)&Bs[0][brow][bcol] = bv;
    }
    __syncthreads();

    int buf = 0;
    for (int k0 = 0; k0 < K; k0 += 8) {
        float4 av, bv;
        bool more = (k0 + 8 < K);
        if (more) {
            av = *(const float4*)(Aptr + k0 + 8);
            bv = *(const float4*)(Bptr + (size_t)(k0 + 8)*Nn);
        }
        #pragma unroll
        for (int kk = 0; kk < 8; kk++) {
            float a[8], bb[8];
            *(float4*)&a[0] = *(const float4*)&As[buf][kk][ty*8];
            *(float4*)&a[4] = *(const float4*)&As[buf][kk][ty*8+4];
            *(float4*)&bb[0] = *(const float4*)&Bs[buf][kk][tx*8];
            *(float4*)&bb[4] = *(const float4*)&Bs[buf][kk][tx*8+4];
            #pragma unroll
            for (int i = 0; i < 8; i++)
                #pragma unroll
                for (int j = 0; j < 8; j++)
                    acc[i][j] = fmaf(a[i], bb[j], acc[i][j]);
        }
        if (more) {
            As[buf^1][acol+0][arow] = av.x;
            As[buf^1][acol+1][arow] = av.y;
            As[buf^1][acol+2][arow] = av.z;
            As[buf^1][acol+3][arow] = av.w;
            *(float4*)&Bs[buf^1][brow][bcol] = bv;
        }
        __syncthreads();
        buf ^= 1;
    }

    if (MODE == 0) {
        #pragma unroll
        for (int i = 0; i < 8; i++) {
            int r = m0 + ty*8 + i;
            int b = r >> 11;
            int n = r & 2047;
            #pragma unroll
            for (int j = 0; j < 8; j++) {
                int c = n0 + tx*8 + j;
                int part = c >> 10;
                int d = c & 1023;
                int h = d >> 6;
                int hd = d & 63;
                float* dst = (part == 0) ? g_q : (part == 1) ? g_k : g_v;
                dst[((((size_t)b*HH + h)*NN + n) << 6) + hd] = acc[i][j];
            }
        }
    } else {
        #pragma unroll
        for (int i = 0; i < 8; i++) {
            int r = m0 + ty*8 + i;
            float* Crow = C + (size_t)r*Nn;
            #pragma unroll
            for (int j = 0; j < 8; j++) {
                int c = n0 + tx*8 + j;
                Crow[c] = acc[i][j] + bias[c];
            }
        }
    }
}

// ---------------- flash attention v2: 128 queries x 128 keys per block ----------------
// 256 threads; thread (ty=tid>>4, tx=tid&15) owns q-tokens {4ty..+3, 64+4ty..+3}
// and k-tokens {4tx..+3, 64+4tx..+3} (S phase) / dims {4tx..+3} (PV phase).
// smem (dynamic, 133120 B):
//   sQ : [64][128] transposed, float4-group XOR swizzle (g ^ (kk&31)),  8192 f
//   sKP: K as [64][128] swizzled (8192 f) reused as P [128][132]       16896 f
//   sV : [128][64] natural                                              8192 f
#define FL_SMEM_FLOATS (8192 + 16896 + 8192)
#define FL_SMEM_BYTES (FL_SMEM_FLOATS * 4)

__global__ __launch_bounds__(256) void flash_kernel() {
    extern __shared__ __align__(16) float sm[];
    float* sQ  = sm;
    float* sKP = sm + 8192;
    float* sV  = sm + 8192 + 16896;

    int tid = threadIdx.x;
    int b = blockIdx.z, h = blockIdx.y;
    int q0 = blockIdx.x * 128;
    const float* Qg = g_q + (((size_t)(b*HH + h))*NN + q0)*HD;
    const float* Kg = g_k + ((size_t)(b*HH + h))*NN*HD;
    const float* Vg = g_v + ((size_t)(b*HH + h))*NN*HD;
    const float* biasg = g_bias + (size_t)(b*HH + h)*NN;
    int ty = tid >> 4, tx = tid & 15;

    int kkld = tid & 63;        // transposed-load: this thread's hd index
    int c4b  = tid >> 6;        // and starting token-group (0..3)

    // Load Q transposed + swizzled: sQ[kk][4*(g ^ (kk&31)) ...] = Q[token][kk]
    #pragma unroll
    for (int r = 0; r < 8; r++) {
        int c4 = c4b + 4*r;
        float4 v;
        v.x = Qg[(size_t)(4*c4 + 0)*HD + kkld];
        v.y = Qg[(size_t)(4*c4 + 1)*HD + kkld];
        v.z = Qg[(size_t)(4*c4 + 2)*HD + kkld];
        v.w = Qg[(size_t)(4*c4 + 3)*HD + kkld];
        *(float4*)&sQ[kkld*128 + 4*(c4 ^ (kkld & 31))] = v;
    }

    float m_run[8], l_run[8], acc[8][4];
    #pragma unroll
    for (int i = 0; i < 8; i++) {
        m_run[i] = -1e30f; l_run[i] = 0.f;
        #pragma unroll
        for (int j = 0; j < 4; j++) acc[i][j] = 0.f;
    }

    for (int c0 = 0; c0 < NN; c0 += 128) {
        // Load K chunk transposed+swizzled; V natural
        #pragma unroll
        for (int r = 0; r < 8; r++) {
            int c4 = c4b + 4*r;
            float4 v;
            v.x = Kg[(size_t)(c0 + 4*c4 + 0)*HD + kkld];
            v.y = Kg[(size_t)(c0 + 4*c4 + 1)*HD + kkld];
            v.z = Kg[(size_t)(c0 + 4*c4 + 2)*HD + kkld];
            v.w = Kg[(size_t)(c0 + 4*c4 + 3)*HD + kkld];
            *(float4*)&sKP[kkld*128 + 4*(c4 ^ (kkld & 31))] = v;
        }
        #pragma unroll
        for (int r = 0; r < 8; r++) {
            int f4i = tid + 256*r;            // 2048 float4s
            int c = f4i >> 4, d4 = f4i & 15;
            *(float4*)&sV[c*64 + 4*d4] =
                *(const float4*)&Vg[(size_t)(c0 + c)*HD + 4*d4];
        }
        float bv[8];
        #pragma unroll
        for (int j = 0; j < 4; j++) {
            bv[j]   = biasg[c0 + 4*tx + j];
            bv[j+4] = biasg[c0 + 64 + 4*tx + j];
        }
        __syncthreads();

        // S = Q K^T (128x128 tile, 8x8 per thread)
        float s[8][8];
        #pragma unroll
        for (int i = 0; i < 8; i++)
            #pragma unroll
            for (int j = 0; j < 8; j++) s[i][j] = 0.f;
        #pragma unroll 4
        for (int kk = 0; kk < 64; kk++) {
            int sw = kk & 31;
            float4 q0v = *(const float4*)&sQ [kk*128 + 4*( ty       ^ sw)];
            float4 q1v = *(const float4*)&sQ [kk*128 + 4*((16 + ty) ^ sw)];
            float4 k0v = *(const float4*)&sKP[kk*128 + 4*( tx       ^ sw)];
            float4 k1v = *(const float4*)&sKP[kk*128 + 4*((16 + tx) ^ sw)];
            float qa[8] = {q0v.x, q0v.y, q0v.z, q0v.w, q1v.x, q1v.y, q1v.z, q1v.w};
            float ka[8] = {k0v.x, k0v.y, k0v.z, k0v.w, k1v.x, k1v.y, k1v.z, k1v.w};
            #pragma unroll
            for (int i = 0; i < 8; i++)
                #pragma unroll
                for (int j = 0; j < 8; j++)
                    s[i][j] = fmaf(qa[i], ka[j], s[i][j]);
        }

        // Online softmax (rows reduce across the 16 tx lanes)
        float ef[8];
        #pragma unroll
        for (int i = 0; i < 8; i++) {
            float rm = -1e30f;
            #pragma unroll
            for (int j = 0; j < 8; j++) {
                s[i][j] = fmaf(s[i][j], SCALE, bv[j]);
                rm = fmaxf(rm, s[i][j]);
            }
            #pragma unroll
            for (int msk = 8; msk >= 1; msk >>= 1)
                rm = fmaxf(rm, __shfl_xor_sync(0xffffffffu, rm, msk));
            float m_new = fmaxf(m_run[i], rm);
            ef[i] = __expf(m_run[i] - m_new);
            float rs = 0.f;
            #pragma unroll
            for (int j = 0; j < 8; j++) {
                s[i][j] = __expf(s[i][j] - m_new);
                rs += s[i][j];
            }
            #pragma unroll
            for (int msk = 8; msk >= 1; msk >>= 1)
                rs += __shfl_xor_sync(0xffffffffu, rs, msk);
            l_run[i] = l_run[i]*ef[i] + rs;
            m_run[i] = m_new;
            #pragma unroll
            for (int j = 0; j < 4; j++) acc[i][j] *= ef[i];
        }

        __syncthreads();   // all reads of K done; safe to overwrite with P
        // Store P [q][c], row stride 132 (natural columns)
        #pragma unroll
        for (int i = 0; i < 8; i++) {
            int q = (i < 4) ? (4*ty + i) : (64 + 4*ty + (i - 4));
            float4 lo = make_float4(s[i][0], s[i][1], s[i][2], s[i][3]);
            float4 hi = make_float4(s[i][4], s[i][5], s[i][6], s[i][7]);
            *(float4*)&sKP[q*132 + 4*tx]      = lo;
            *(float4*)&sKP[q*132 + 64 + 4*tx] = hi;
        }
        __syncthreads();

        // acc += P @ V (thread: 8 q rows x dims 4tx..4tx+3)
        #pragma unroll 2
        for (int c4 = 0; c4 < 32; c4++) {
            float4 v0 = *(const float4*)&sV[(4*c4 + 0)*64 + 4*tx];
            float4 v1 = *(const float4*)&sV[(4*c4 + 1)*64 + 4*tx];
            float4 v2 = *(const float4*)&sV[(4*c4 + 2)*64 + 4*tx];
            float4 v3 = *(const float4*)&sV[(4*c4 + 3)*64 + 4*tx];
            #pragma unroll
            for (int i = 0; i < 8; i++) {
                int q = (i < 4) ? (4*ty + i) : (64 + 4*ty + (i - 4));
                float4 pv = *(const float4*)&sKP[q*132 + 4*c4];
                acc[i][0] = fmaf(pv.x, v0.x, acc[i][0]);
                acc[i][1] = fmaf(pv.x, v0.y, acc[i][1]);
                acc[i][2] = fmaf(pv.x, v0.z, acc[i][2]);
                acc[i][3] = fmaf(pv.x, v0.w, acc[i][3]);
                acc[i][0] = fmaf(pv.y, v1.x, acc[i][0]);
                acc[i][1] = fmaf(pv.y, v1.y, acc[i][1]);
                acc[i][2] = fmaf(pv.y, v1.z, acc[i][2]);
                acc[i][3] = fmaf(pv.y, v1.w, acc[i][3]);
                acc[i][0] = fmaf(pv.z, v2.x, acc[i][0]);
                acc[i][1] = fmaf(pv.z, v2.y, acc[i][1]);
                acc[i][2] = fmaf(pv.z, v2.z, acc[i][2]);
                acc[i][3] = fmaf(pv.z, v2.w, acc[i][3]);
                acc[i][0] = fmaf(pv.w, v3.x, acc[i][0]);
                acc[i][1] = fmaf(pv.w, v3.y, acc[i][1]);
                acc[i][2] = fmaf(pv.w, v3.z, acc[i][2]);
                acc[i][3] = fmaf(pv.w, v3.w, acc[i][3]);
            }
        }
        __syncthreads();   // before next chunk overwrites sKP/sV
    }

    // normalize and write [b][n][h*64 + 4tx]
    #pragma unroll
    for (int i = 0; i < 8; i++) {
        int q = (i < 4) ? (4*ty + i) : (64 + 4*ty + (i - 4));
        float inv = 1.0f / l_run[i];
        float4 o;
        o.x = acc[i][0]*inv; o.y = acc[i][1]*inv;
        o.z = acc[i][2]*inv; o.w = acc[i][3]*inv;
        *(float4*)&g_attnout[((size_t)b*NN + q0 + q)*DD + h*HD + 4*tx] = o;
    }
}

// ---------------- launch ----------------
extern "C" void kernel_launch(void* const* d_in, const int* in_sizes, int n_in,
                              void* d_out, int out_size) {
    const float* x        = (const float*)d_in[0];
    const float* coverage = (const float*)d_in[1];
    const float* w_qkv    = (const float*)d_in[2];
    const float* w_out    = (const float*)d_in[3];
    const float* b_out    = (const float*)d_in[4];
    const float* w_ce1    = (const float*)d_in[5];
    const float* b_ce1    = (const float*)d_in[6];
    const float* w_ce2    = (const float*)d_in[7];
    const float* b_ce2    = (const float*)d_in[8];
    const float* w_fg1    = (const float*)d_in[9];
    const float* b_fg1    = (const float*)d_in[10];
    const float* w_fg2    = (const float*)d_in[11];
    const float* b_fg2    = (const float*)d_in[12];
    float* out = (float*)d_out;

    cudaFuncSetAttribute(flash_kernel,
        cudaFuncAttributeMaxDynamicSharedMemorySize, FL_SMEM_BYTES);

    // pooled gate path
    zero_pooled_kernel<<<(BB*DD + 255)/256, 256>>>();
    pool_kernel<<<dim3(DD/256, BB, NN/128), 256>>>(x);
    gate_kernel<<<BB, 256>>>(w_fg1, b_fg1, w_fg2, b_fg2);
    // coverage bias (needs gate)
    cov_kernel2<<<dim3(NN/4, BB), 128>>>(coverage, w_ce1, b_ce1, w_ce2, b_ce2);
    // QKV projection
    sgemm_kernel<0><<<dim3(3*DD/128, BB*NN/128), 256>>>(x, w_qkv, nullptr, nullptr, 3*DD);
    // fused attention
    flash_kernel<<<dim3(NN/128, HH, BB), 256, FL_SMEM_BYTES>>>();
    // output projection
    sgemm_kernel<1><<<dim3(DD/128, BB*NN/128), 256>>>(nullptr, w_out, out, b_out, DD);
}